// round 4
// baseline (speedup 1.0000x reference)
#include <cuda_runtime.h>
#include <cstdint>

#define TOPK      2000
#define NMS_THR   0.5f
#define MAXN      200000
#define MAXG      128
#define HBINS     65536
#define CAP       8192
#define CBLK      32          // ceil(TOPK/64)
#define BM        256         // proposals per block in main kernel

typedef unsigned long long ull;

// ---------------- scratch (no allocation allowed) ----------------
__device__ float               g_score[MAXN];
__device__ float4              g_boxper[MAXN];
__device__ __align__(16) int   g_hist[HBINS];   // zeroed at load; re-zeroed (parallel) in K2
__device__ int                 g_candcount;     // zeroed at load; reset in K2 sort block
__device__ int                 g_binB;
__device__ ull                 g_cand[CAP];
__device__ float4              g_topboxes[TOPK];
__device__ ull                 g_mask[TOPK * CBLK];
__device__ int                 g_done1, g_done2, g_done3;   // zero at load; self-resetting

// =================== K1: fused per-proposal + last-block findbin ==========
__global__ void __launch_bounds__(BM) main_kernel(
        const float4* __restrict__ prop,
        const float4* __restrict__ btp,   // (N*C) float4
        const float*  __restrict__ cls,
        const float4* __restrict__ gt,
        const int* __restrict__ ihp,
        const int* __restrict__ iwp,
        float4* __restrict__ out,         // full output, rows (TOPK+n)
        int N, int C, int G)
{
    __shared__ float4 sgtb[MAXG];
    __shared__ float  sga[MAXG];
    __shared__ int    is_last;
    extern __shared__ float scls[];       // BM*21 floats (stride 21 -> conflict-free)

    int tid = threadIdx.x;
    int n0  = blockIdx.x * BM;

    int vi = ihp[0];
    float H = (vi > 0 && vi < 1000000) ? (float)vi : __int_as_float(vi);
    vi = iwp[0];
    float W = (vi > 0 && vi < 1000000) ? (float)vi : __int_as_float(vi);

    for (int i = tid; i < G && i < MAXG; i += BM) {
        float4 g = gt[i];
        sgtb[i] = g;
        sga[i]  = (g.z - g.x) * (g.w - g.y);
    }
    // stage cls rows (coalesced global reads)
    {
        int rows = min(BM, N - n0);
        if (rows > 0) {
            const float* cbase = cls + (size_t)n0 * C;
            if (C == 21) {
                int total = rows * 21;
                for (int idx = tid; idx < total; idx += BM) {
                    int r = idx / 21;
                    scls[r * 21 + (idx - r * 21)] = cbase[idx];
                }
            } else {
                int total = rows * C;
                for (int idx = tid; idx < total; idx += BM) {
                    int r = idx / C;
                    scls[r * 21 + (idx - r * C)] = cbase[idx];
                }
            }
        }
    }
    __syncthreads();

    int n = n0 + tid;
    if (n < N) {
        float4 p = prop[n];
        float pw = p.z - p.x, ph = p.w - p.y;
        float pcx = p.x + 0.5f * pw, pcy = p.y + 0.5f * ph;
        float parea = pw * ph;

        // softmax score + fg argmax (from shared)
        const float* cr = scls + tid * 21;
        float m = cr[0], bl = -1e30f; int bc = 1;
        #pragma unroll
        for (int c = 1; c < 21; c++) {
            float v = cr[c];
            m = fmaxf(m, v);
            if (v > bl) { bl = v; bc = c; }
        }
        float Z = 0.f;
        #pragma unroll
        for (int c = 0; c < 21; c++) Z += __expf(cr[c] - m);
        float score = __fdividef(__expf(bl - m), Z);

        // decode selected class box, clamp
        float4 t = btp[(size_t)n * C + bc];
        float dcx = t.x * pw + pcx;
        float dcy = t.y * ph + pcy;
        float dw  = __expf(t.z) * pw;
        float dh  = __expf(t.w) * ph;
        float4 box;
        box.x = fminf(fmaxf(dcx - 0.5f * dw, 0.f), W);
        box.y = fminf(fmaxf(dcy - 0.5f * dh, 0.f), H);
        box.z = fminf(fmaxf(dcx + 0.5f * dw, 0.f), W);
        box.w = fminf(fmaxf(dcy + 0.5f * dh, 0.f), H);

        g_boxper[n] = box;
        g_score[n]  = score;
        atomicAdd(&g_hist[__float_as_uint(score) >> 16], 1);

        // best-IoU gt match: argmax via cross-multiply (no division)
        float bnum = -1.0f, bden = 1.0f; int bg = 0;
        #pragma unroll 4
        for (int g = 0; g < G; g++) {
            float4 gb = sgtb[g];
            float lx = fmaxf(gb.x, p.x);
            float ly = fmaxf(gb.y, p.y);
            float rx = fminf(gb.z, p.z);
            float ry = fminf(gb.w, p.w);
            float iw = fmaxf(rx - lx, 0.f), ihh = fmaxf(ry - ly, 0.f);
            float inter = iw * ihh;
            float den = sga[g] + parea - inter;
            if (inter * bden > bnum * den) { bnum = inter; bden = den; bg = g; }
        }
        float4 gb = sgtb[bg];
        float gw = gb.z - gb.x, gh = gb.w - gb.y;
        float gcx = gb.x + 0.5f * gw, gcy = gb.y + 0.5f * gh;
        float4 rt;
        rt.x = __fdividef(gcx - pcx, pw);
        rt.y = __fdividef(gcy - pcy, ph);
        rt.z = __logf(__fdividef(gw, pw));
        rt.w = __logf(__fdividef(gh, ph));
        out[TOPK + n] = rt;
    }

    // -------- last finishing block computes the histogram cutoff ----------
    __syncthreads();
    if (tid == 0) {
        __threadfence();
        is_last = (atomicAdd(&g_done1, 1) == gridDim.x - 1);
    }
    __syncthreads();
    if (!is_last) return;
    if (tid == 0) g_done1 = 0;

    // reuse dynamic smem: csum[1024] chunk sums + sc[256] scan
    int* csum = (int*)scls;
    int* sc   = csum + 1024;
    int w = tid >> 5, lane = tid & 31;
    for (int c = w; c < 1024; c += 8) {           // 8 warps, warp per chunk
        int base = HBINS - (c + 1) * 64;          // chunk c: 64 bins, c=0 is top
        int s = g_hist[base + lane] + g_hist[base + 32 + lane];
        s = __reduce_add_sync(0xFFFFFFFFu, s);
        if (lane == 0) csum[c] = s;
    }
    __syncthreads();
    int local = csum[4*tid] + csum[4*tid+1] + csum[4*tid+2] + csum[4*tid+3];
    sc[tid] = local;
    __syncthreads();
    for (int off = 1; off < 256; off <<= 1) {
        int add = (tid >= off) ? sc[tid - off] : 0;
        __syncthreads();
        sc[tid] += add;
        __syncthreads();
    }
    int incl = sc[tid], excl = incl - local;
    if (excl < TOPK && incl >= TOPK) {            // unique thread
        int run = excl;
        for (int c = 4 * tid; c < 4 * tid + 4; c++) {
            if (run + csum[c] >= TOPK) {
                int hi = HBINS - 64 * c - 1;
                for (int b = hi; b > hi - 64; b--) {
                    run += g_hist[b];
                    if (run >= TOPK) { g_binB = b; break; }
                }
                break;
            }
            run += csum[c];
        }
    }
}

// =================== K2: compact + hist zero + last-block sort ============
__global__ void __launch_bounds__(1024) compact_sort_kernel(int N) {
    extern __shared__ ull sk[];
    __shared__ int is_last;
    int tid = threadIdx.x;
    int gid = blockIdx.x * 1024 + tid;

    if (gid < N) {
        unsigned bits = __float_as_uint(g_score[gid]);
        if ((int)(bits >> 16) >= g_binB) {
            int pos = atomicAdd(&g_candcount, 1);
            if (pos < CAP)
                g_cand[pos] = ((ull)bits << 32) | (unsigned)(~gid);
        }
    }
    if (gid < HBINS) g_hist[gid] = 0;            // parallel re-zero for next replay

    __syncthreads();
    if (tid == 0) {
        __threadfence();
        is_last = (atomicAdd(&g_done2, 1) == gridDim.x - 1);
    }
    __syncthreads();
    if (!is_last) return;
    if (tid == 0) g_done2 = 0;

    int M = g_candcount; if (M > CAP) M = CAP;
    int P = 2048;
    while (P < M) P <<= 1;
    for (int i = tid; i < P; i += 1024)
        sk[i] = (i < M) ? g_cand[i] : 0ULL;
    __syncthreads();
    if (tid == 0) g_candcount = 0;               // reset after M consumed
    for (int k = 2; k <= P; k <<= 1) {
        for (int j = k >> 1; j > 0; j >>= 1) {
            for (int i = tid; i < P; i += 1024) {
                int l = i ^ j;
                if (l > i) {
                    bool desc = ((i & k) == 0);
                    ull a = sk[i], b = sk[l];
                    if (desc ? (a < b) : (a > b)) { sk[i] = b; sk[l] = a; }
                }
            }
            __syncthreads();
        }
    }
    for (int i = tid; i < TOPK; i += 1024) {
        unsigned n = ~(unsigned)(sk[i] & 0xFFFFFFFFULL);
        g_topboxes[i] = g_boxper[n];
    }
}

// =================== K3: NMS masks + last-block greedy scan + write =======
__global__ void __launch_bounds__(256) nms_kernel(float* __restrict__ out) {
    __shared__ float4 sb[64];
    __shared__ int is_last;
    __shared__ ull skeep[CBLK];
    int cb = blockIdx.x;
    int t  = threadIdx.x;
    int col0 = cb * 64;
    if (t < 64 && col0 + t < TOPK) sb[t] = g_topboxes[col0 + t];
    __syncthreads();
    int row = blockIdx.y * 256 + t;
    if (row < TOPK) {
        float4 a = g_topboxes[row];
        float aarea = (a.z - a.x) * (a.w - a.y);
        ull bits = 0;
        int nj = min(64, TOPK - col0);
        for (int j = 0; j < nj; j++) {
            float4 b = sb[j];
            float lx = fmaxf(a.x, b.x), ly = fmaxf(a.y, b.y);
            float rx = fminf(a.z, b.z), ry = fminf(a.w, b.w);
            float iw = fmaxf(rx - lx, 0.f), ih = fmaxf(ry - ly, 0.f);
            float inter = iw * ih;
            float barea = (b.z - b.x) * (b.w - b.y);
            float iou = __fdividef(inter, aarea + barea - inter);
            if (iou > NMS_THR) bits |= (1ULL << j);   // NaN compares false
        }
        g_mask[row * CBLK + cb] = bits;
    }

    __syncthreads();
    if (t == 0) {
        __threadfence();
        is_last = (atomicAdd(&g_done3, 1) == (int)(gridDim.x * gridDim.y) - 1);
    }
    __syncthreads();
    if (!is_last) return;
    if (t == 0) g_done3 = 0;

    // greedy scan: 1 warp, pipelined mask prefetch, short serial ALU chain
    if (t < 32) {
        ull rem = 0;        // lane t: OR of suppression for column block t
        ull cur_sup = 0;    // replicated: suppression word of current 64-row block
        ull kw = 0;         // keep bits of current block (replicated)
        ull bit = 1;
        const int D = 8;
        ull buf[D];
        #pragma unroll
        for (int k = 0; k < D; k++) buf[k] = g_mask[k * CBLK + t];
        ull m0 = __shfl_sync(0xFFFFFFFFu, buf[0], 0);
        ull m1 = __shfl_sync(0xFFFFFFFFu, buf[1], 0);
        for (int i = 0; i < TOPK; i++) {
            ull cur = buf[i & (D - 1)];
            ull m2 = 0;
            if (i + 2 < TOPK)
                m2 = __shfl_sync(0xFFFFFFFFu, buf[(i + 2) & (D - 1)], (i + 2) >> 6);
            if (i + D < TOPK) buf[i & (D - 1)] = g_mask[(i + D) * CBLK + t];

            bool keep = (cur_sup & bit) == 0ULL;
            if (keep) { cur_sup |= m0; kw |= bit; }
            rem |= keep ? cur : 0ULL;

            if ((i & 63) == 63) {
                if (t == 0) skeep[i >> 6] = kw;
                kw = 0; bit = 1;
                cur_sup = __shfl_sync(0xFFFFFFFFu, rem, (i + 1) >> 6);
            } else {
                bit <<= 1;
            }
            m0 = m1; m1 = m2;
        }
        if (t == 0) skeep[(TOPK - 1) >> 6] = kw;
    }
    __syncthreads();
    const float* tb = (const float*)g_topboxes;
    for (int idx = t; idx < TOPK * 4; idx += 256) {
        int r = idx >> 2;
        float k = ((skeep[r >> 6] >> (r & 63)) & 1ULL) ? 1.0f : 0.0f;
        out[idx] = tb[idx] * k;
    }
}

// ---------------- launcher: 3 graph nodes ----------------
extern "C" void kernel_launch(void* const* d_in, const int* in_sizes, int n_in,
                              void* d_out, int out_size)
{
    const float4* prop = (const float4*)d_in[0];
    const float4* btp  = (const float4*)d_in[1];
    const float*  cls  = (const float*)d_in[2];
    const float4* gt   = (const float4*)d_in[3];
    const int*    ih   = (const int*)d_in[4];
    const int*    iw   = (const int*)d_in[5];
    float*        out  = (float*)d_out;

    int N = in_sizes[0] / 4;
    int C = in_sizes[2] / N;
    int G = in_sizes[3] / 4;

    static int smem_set = 0;
    if (!smem_set) {
        cudaFuncSetAttribute(compact_sort_kernel,
                             cudaFuncAttributeMaxDynamicSharedMemorySize,
                             CAP * (int)sizeof(ull));
        smem_set = 1;
    }

    int smem_main = BM * 21 * (int)sizeof(float);
    main_kernel<<<(N + BM - 1) / BM, BM, smem_main>>>(
        prop, btp, cls, gt, ih, iw, (float4*)out, N, C, G);

    compact_sort_kernel<<<(N + 1023) / 1024, 1024, CAP * sizeof(ull)>>>(N);

    dim3 grid((TOPK + 63) / 64, (TOPK + 255) / 256);
    nms_kernel<<<grid, 256>>>(out);
}